// round 3
// baseline (speedup 1.0000x reference)
#include <cuda_runtime.h>
#include <math.h>

// Fixed problem shapes
#define BB    8
#define NA    5
#define NC    8
#define NH    192
#define NW    192
#define TT    50
#define ATTRS 15                 // 7 + NC
#define NHW   (NH*NW)            // 36864
#define CELLS (BB*NA*NHW)        // 1,474,560
#define NT    (BB*TT)            // 400
#define NIGN  (NT*NA)            // 2000

#define TPB       256
#define CPT       4
#define NB_DENSE  (CELLS/(CPT*TPB))   // 1440 (exact)
#define HASH_SZ   4096
#define HASH_MASK (HASH_SZ-1)

// ---- persistent device scratch (re-initialized by K1 every replay) ----
__device__ double       g_S0;       // dense softplus sum
__device__ double       g_corr[7];  // 0:noobjCorr 1:objconf 2..5:coords 6:ce
__device__ int          g_nObj, g_removed;
__device__ unsigned int g_ticket;

__device__ __forceinline__ float sp_fast(float v) {      // softplus == bce0 (clip never binds for |v|<16)
    return fmaxf(v, 0.f) + __logf(1.f + __expf(-fabsf(v)));
}
__device__ __forceinline__ float sigf(float v) {
    return 1.f / (1.f + __expf(-v));
}
__device__ __forceinline__ unsigned hash_cell(int cell) {
    return (((unsigned)cell * 2654435761u) >> 16) & HASH_MASK;
}

// ================= K1: targets + sparse corrections (one block) =================
__global__ void k_sparse(const float* __restrict__ x,
                         const float* __restrict__ tg,
                         const float* __restrict__ anchors)
{
    __shared__ int    s_hash[HASH_SZ];
    __shared__ int    s_meta[NT];     // valid<<28 | best<<16 | gj<<8 | gi
    __shared__ int    s_label[NT];
    __shared__ float  s_fx[NT], s_fy[NT], s_tw[NT], s_th[NT], s_gw[NT], s_gh[NT];
    __shared__ double s_acc[7];
    __shared__ int    s_nObj, s_nIgn;
    __shared__ float  s_anchor[2*NA];

    const int tid = threadIdx.x;

    for (int i = tid; i < HASH_SZ; i += TPB) s_hash[i] = -1;
    if (tid < 7) s_acc[tid] = 0.0;
    if (tid == 0) { s_nObj = 0; s_nIgn = 0; g_S0 = 0.0; g_ticket = 0u; }
    if (tid < 2*NA) s_anchor[tid] = anchors[tid];
    __syncthreads();

    // phase 0: per-target precompute
    for (int t = tid; t < NT; t += TPB) {
        const float* r = tg + (size_t)t * 5;
        float r0 = r[0], r1 = r[1], r2 = r[2], r3 = r[3], r4 = r[4];
        int valid = ((r0 + r1 + r2 + r3 + r4) != 0.f);
        float gx = r1 * NW, gy = r2 * NH, gw = r3 * NW, gh = r4 * NH;
        int gi = (int)floorf(gx), gj = (int)floorf(gy);
        float bestIou = -1.f; int best = 0; float awb = 1.f, ahb = 1.f;
        #pragma unroll
        for (int a = 0; a < NA; a++) {
            float aw = s_anchor[2*a], ah = s_anchor[2*a+1];
            float inter = fminf(gw, aw) * fminf(gh, ah);
            float iou   = inter / (gw * gh + aw * ah - inter);
            if (iou > bestIou) { bestIou = iou; best = a; awb = aw; ahb = ah; }
        }
        s_meta[t]  = (valid << 28) | (best << 16) | (gj << 8) | gi;
        s_label[t] = (int)r0;
        s_fx[t] = gx - floorf(gx);
        s_fy[t] = gy - floorf(gy);
        s_tw[t] = logf(gw / awb + 1e-16f);
        s_th[t] = logf(gh / ahb + 1e-16f);
        s_gw[t] = gw; s_gh[t] = gh;
    }
    __syncthreads();

    // phase 1: winners (last-write-wins) -> hash insert + obj-cell corrections
    for (int t = tid; t < NT; t += TPB) {
        int meta = s_meta[t];
        if (!(meta >> 28)) continue;
        int b = t / TT;
        bool winner = true;
        int tEnd = (b + 1) * TT;
        for (int t2 = t + 1; t2 < tEnd; t2++)
            if (s_meta[t2] == meta) { winner = false; break; }
        if (!winner) continue;

        int best = (meta >> 16) & 0xff, gj = (meta >> 8) & 0xff, gi = meta & 0xff;
        int cell = ((b * NA + best) * NH + gj) * NW + gi;
        unsigned h = hash_cell(cell);
        while (atomicCAS(&s_hash[h], -1, cell) != -1) h = (h + 1) & HASH_MASK;
        atomicAdd(&s_nObj, 1);

        size_t base = (size_t)(b * NA + best) * ATTRS * NHW + (size_t)gj * NW + gi;
        float x0 = x[base];
        float x1 = x[base + (size_t)NHW];
        float x2 = x[base + 2 * (size_t)NHW];
        float x3 = x[base + 3 * (size_t)NHW];
        float xc = x[base + 6 * (size_t)NHW];

        float dx = sigf(x0) - s_fx[t];
        float dy = sigf(x1) - s_fy[t];
        float dw = x2 - s_tw[t];
        float dh = x3 - s_th[t];
        atomicAdd(&s_acc[2], (double)(dx * dx));
        atomicAdd(&s_acc[3], (double)(dy * dy));
        atomicAdd(&s_acc[4], (double)(dw * dw));
        atomicAdd(&s_acc[5], (double)(dh * dh));
        atomicAdd(&s_acc[1], (double)sp_fast(-xc));   // -log p (tconf=1 bce)
        atomicAdd(&s_acc[0], -(double)sp_fast(xc));   // remove bce0 from noobj sum

        // class CE: log_softmax over sigmoid(logits)
        float sv[NC]; float m = -1e30f;
        #pragma unroll
        for (int c = 0; c < NC; c++) {
            sv[c] = sigf(x[base + (size_t)(7 + c) * NHW]);
            m = fmaxf(m, sv[c]);
        }
        float sum = 0.f;
        #pragma unroll
        for (int c = 0; c < NC; c++) sum += __expf(sv[c] - m);
        float ce = m + __logf(sum) - sv[s_label[t]];
        atomicAdd(&s_acc[6], (double)ce);
    }
    __syncthreads();   // all obj cells in hash before ignore probes

    // phase 2: ignore cells (iou > 0.6), dedup via hash; obj beats ignore
    for (int k = tid; k < NIGN; k += TPB) {
        int t = k / NA, a = k % NA;
        int meta = s_meta[t];
        if (!(meta >> 28)) continue;
        float aw = s_anchor[2*a], ah = s_anchor[2*a+1];
        float gw = s_gw[t], gh = s_gh[t];
        float inter = fminf(gw, aw) * fminf(gh, ah);
        float iou   = inter / (gw * gh + aw * ah - inter);
        if (!(iou > 0.6f)) continue;
        int b = t / TT, gj = (meta >> 8) & 0xff, gi = meta & 0xff;
        int cell = ((b * NA + a) * NH + gj) * NW + gi;
        unsigned h = hash_cell(cell);
        bool mine = false;
        while (true) {
            int prev = atomicCAS(&s_hash[h], -1, cell);
            if (prev == -1)   { mine = true; break; }
            if (prev == cell) break;                    // dup or obj cell
            h = (h + 1) & HASH_MASK;
        }
        if (!mine) continue;
        atomicAdd(&s_nIgn, 1);
        float xc = x[((size_t)(b * NA + a) * ATTRS + 6) * NHW + (size_t)gj * NW + gi];
        atomicAdd(&s_acc[0], -(double)sp_fast(xc));
    }
    __syncthreads();
    if (tid == 0) {
        #pragma unroll
        for (int i = 0; i < 7; i++) g_corr[i] = s_acc[i];
        g_nObj    = s_nObj;
        g_removed = s_nObj + s_nIgn;
    }
}

// ================= K2: dense softplus sum + last-block finalize =================
__global__ void __launch_bounds__(TPB)
k_dense(const float* __restrict__ x, float* __restrict__ out)
{
    __shared__ float s_warp[TPB/32];
    __shared__ int   s_isLast;

    const int tid = threadIdx.x;
    int idx = blockIdx.x * TPB + tid;        // one thread = 4 cells, exact cover
    int c4  = idx * CPT;
    int i0  = c4 % NW;
    int j   = (c4 / NW) % NH;
    int ba  = c4 / NHW;
    float4 v = *(const float4*)(x + ((size_t)ba * ATTRS + 6) * NHW + (size_t)j * NW + i0);
    float local = sp_fast(v.x) + sp_fast(v.y) + sp_fast(v.z) + sp_fast(v.w);

    #pragma unroll
    for (int o = 16; o; o >>= 1) local += __shfl_down_sync(0xffffffffu, local, o);
    if ((tid & 31) == 0) s_warp[tid >> 5] = local;
    __syncthreads();

    if (tid == 0) {
        float bs = 0.f;
        #pragma unroll
        for (int w = 0; w < TPB/32; w++) bs += s_warp[w];
        atomicAdd(&g_S0, (double)bs);             // REDG.F64, no return
        __threadfence();
        unsigned old = atomicAdd(&g_ticket, 1u);
        s_isLast = (old == (unsigned)(NB_DENSE - 1));
    }
    __syncthreads();

    if (s_isLast && tid == 0) {
        double S0   = g_S0 + g_corr[0];
        double nobj = (double)g_nObj;
        double cnt  = (double)CELLS - (double)g_removed;
        double loss = (g_corr[2] + g_corr[3] + g_corr[4] + g_corr[5]
                       + g_corr[1] + g_corr[6] / (double)BB) / nobj
                    + S0 / cnt;
        out[0] = (float)loss;
    }
}

extern "C" void kernel_launch(void* const* d_in, const int* in_sizes, int n_in,
                              void* d_out, int out_size) {
    const float* x  = (const float*)d_in[0];
    const float* tg = (const float*)d_in[1];
    const float* an = (const float*)d_in[2];
    k_sparse<<<1, TPB>>>(x, tg, an);
    k_dense<<<NB_DENSE, TPB>>>(x, (float*)d_out);
}

// round 4
// speedup vs baseline: 1.5439x; 1.5439x over previous
#include <cuda_runtime.h>
#include <math.h>

// Fixed problem shapes
#define BB    8
#define NA    5
#define NC    8
#define NH    192
#define NW    192
#define TT    50
#define ATTRS 15                 // 7 + NC
#define NHW   (NH*NW)            // 36864
#define CELLS (BB*NA*NHW)        // 1,474,560
#define NT    (BB*TT)            // 400
#define NIGN  (NT*NA)            // 2000

#define TPB       256
#define CPT       8
#define NB_DENSE  (CELLS/(CPT*TPB))   // 720 (exact)
#define HASH_SZ   4096
#define HASH_MASK (HASH_SZ-1)
#define NWARP     (TPB/32)

// ---- persistent device scratch ----
// g_S0 invariant: 0 at entry to k_dense (static init first call; k_sparse resets it each replay)
__device__ double g_S0 = 0.0;

__device__ __forceinline__ float sp_fast(float v) {   // softplus == bce0 (clip never binds for |v|<16)
    return fmaxf(v, 0.f) + __logf(1.f + __expf(-fabsf(v)));
}
__device__ __forceinline__ float sigf(float v) {
    return 1.f / (1.f + __expf(-v));
}
__device__ __forceinline__ unsigned hash_cell(int cell) {
    return (((unsigned)cell * 2654435761u) >> 16) & HASH_MASK;
}

// ================= K1 (runs FIRST): dense softplus sum over conf channel =================
__global__ void __launch_bounds__(TPB)
k_dense(const float* __restrict__ x)
{
    __shared__ float s_warp[NWARP];
    const int tid = threadIdx.x;
    int c0 = (blockIdx.x * TPB + tid) * CPT;           // exact cover, CPT=8
    int i0 = c0 % NW;
    int j  = (c0 / NW) % NH;
    int ba = c0 / NHW;
    const float* p = x + ((size_t)ba * ATTRS + 6) * NHW + (size_t)j * NW + i0;
    float4 a = *(const float4*)p;
    float4 b = *(const float4*)(p + 4);                // independent -> MLP=2
    float local = (sp_fast(a.x) + sp_fast(a.y)) + (sp_fast(a.z) + sp_fast(a.w))
                + (sp_fast(b.x) + sp_fast(b.y)) + (sp_fast(b.z) + sp_fast(b.w));

    #pragma unroll
    for (int o = 16; o; o >>= 1) local += __shfl_down_sync(0xffffffffu, local, o);
    if ((tid & 31) == 0) s_warp[tid >> 5] = local;
    __syncthreads();
    if (tid == 0) {
        float bs = 0.f;
        #pragma unroll
        for (int w = 0; w < NWARP; w++) bs += s_warp[w];
        atomicAdd(&g_S0, (double)bs);                  // native global f64 red
    }
}

// ================= K2 (runs SECOND): targets + sparse corrections + finalize =================
__global__ void k_sparse(const float* __restrict__ x,
                         const float* __restrict__ tg,
                         const float* __restrict__ anchors,
                         float* __restrict__ out)
{
    __shared__ int    s_hash[HASH_SZ];
    __shared__ int    s_meta[NT];     // valid<<28 | best<<16 | gj<<8 | gi
    __shared__ int    s_label[NT];
    __shared__ float  s_fx[NT], s_fy[NT], s_tw[NT], s_th[NT], s_gw[NT], s_gh[NT];
    __shared__ double s_part[NWARP][7];
    __shared__ int    s_nObj, s_nIgn;
    __shared__ float  s_anchor[2*NA];

    const int tid  = threadIdx.x;
    const int lane = tid & 31;
    const int wid  = tid >> 5;

    // per-thread register accumulators (NO shared f64 atomics)
    double a0 = 0.0, a1 = 0.0, a2 = 0.0, a3 = 0.0, a4 = 0.0, a5 = 0.0, a6 = 0.0;

    for (int i = tid; i < HASH_SZ; i += TPB) s_hash[i] = -1;
    if (tid == 0) { s_nObj = 0; s_nIgn = 0; }
    if (tid < 2*NA) s_anchor[tid] = anchors[tid];
    __syncthreads();

    // phase 0: per-target precompute
    for (int t = tid; t < NT; t += TPB) {
        const float* r = tg + (size_t)t * 5;
        float r0 = r[0], r1 = r[1], r2 = r[2], r3 = r[3], r4 = r[4];
        int valid = ((r0 + r1 + r2 + r3 + r4) != 0.f);
        float gx = r1 * NW, gy = r2 * NH, gw = r3 * NW, gh = r4 * NH;
        int gi = (int)floorf(gx), gj = (int)floorf(gy);
        float bestIou = -1.f; int best = 0; float awb = 1.f, ahb = 1.f;
        #pragma unroll
        for (int a = 0; a < NA; a++) {
            float aw = s_anchor[2*a], ah = s_anchor[2*a+1];
            float inter = fminf(gw, aw) * fminf(gh, ah);
            float iou   = inter / (gw * gh + aw * ah - inter);
            if (iou > bestIou) { bestIou = iou; best = a; awb = aw; ahb = ah; }
        }
        s_meta[t]  = (valid << 28) | (best << 16) | (gj << 8) | gi;
        s_label[t] = (int)r0;
        s_fx[t] = gx - floorf(gx);
        s_fy[t] = gy - floorf(gy);
        s_tw[t] = logf(gw / awb + 1e-16f);
        s_th[t] = logf(gh / ahb + 1e-16f);
        s_gw[t] = gw; s_gh[t] = gh;
    }
    __syncthreads();

    // phase 1: winners (last-write-wins) -> hash insert + obj-cell corrections
    for (int t = tid; t < NT; t += TPB) {
        int meta = s_meta[t];
        if (!(meta >> 28)) continue;
        int b = t / TT;
        bool winner = true;
        int tEnd = (b + 1) * TT;
        for (int t2 = t + 1; t2 < tEnd; t2++)
            if (s_meta[t2] == meta) { winner = false; break; }
        if (!winner) continue;

        int best = (meta >> 16) & 0xff, gj = (meta >> 8) & 0xff, gi = meta & 0xff;
        int cell = ((b * NA + best) * NH + gj) * NW + gi;
        unsigned h = hash_cell(cell);
        while (atomicCAS(&s_hash[h], -1, cell) != -1) h = (h + 1) & HASH_MASK;
        atomicAdd(&s_nObj, 1);                          // int ATOMS: native, fast

        size_t base = (size_t)(b * NA + best) * ATTRS * NHW + (size_t)gj * NW + gi;
        float x0 = x[base];
        float x1 = x[base + (size_t)NHW];
        float x2 = x[base + 2 * (size_t)NHW];
        float x3 = x[base + 3 * (size_t)NHW];
        float xc = x[base + 6 * (size_t)NHW];

        float dx = sigf(x0) - s_fx[t];
        float dy = sigf(x1) - s_fy[t];
        float dw = x2 - s_tw[t];
        float dh = x3 - s_th[t];
        a2 += (double)(dx * dx);
        a3 += (double)(dy * dy);
        a4 += (double)(dw * dw);
        a5 += (double)(dh * dh);
        a1 += (double)sp_fast(-xc);                     // -log p (tconf=1 bce)
        a0 -= (double)sp_fast(xc);                      // remove bce0 from noobj sum

        // class CE: log_softmax over sigmoid(logits)
        float sv[NC]; float m = -1e30f;
        #pragma unroll
        for (int c = 0; c < NC; c++) {
            sv[c] = sigf(x[base + (size_t)(7 + c) * NHW]);
            m = fmaxf(m, sv[c]);
        }
        float sum = 0.f;
        #pragma unroll
        for (int c = 0; c < NC; c++) sum += __expf(sv[c] - m);
        a6 += (double)(m + __logf(sum) - sv[s_label[t]]);
    }
    __syncthreads();   // all obj cells in hash before ignore probes

    // phase 2: ignore cells (iou > 0.6), dedup via hash; obj beats ignore
    for (int k = tid; k < NIGN; k += TPB) {
        int t = k / NA, a = k % NA;
        int meta = s_meta[t];
        if (!(meta >> 28)) continue;
        float aw = s_anchor[2*a], ah = s_anchor[2*a+1];
        float gw = s_gw[t], gh = s_gh[t];
        float inter = fminf(gw, aw) * fminf(gh, ah);
        float iou   = inter / (gw * gh + aw * ah - inter);
        if (!(iou > 0.6f)) continue;
        int b = t / TT, gj = (meta >> 8) & 0xff, gi = meta & 0xff;
        int cell = ((b * NA + a) * NH + gj) * NW + gi;
        unsigned h = hash_cell(cell);
        bool mine = false;
        while (true) {
            int prev = atomicCAS(&s_hash[h], -1, cell);
            if (prev == -1)   { mine = true; break; }
            if (prev == cell) break;                    // dup or obj cell
            h = (h + 1) & HASH_MASK;
        }
        if (!mine) continue;
        atomicAdd(&s_nIgn, 1);
        float xc = x[((size_t)(b * NA + a) * ATTRS + 6) * NHW + (size_t)gj * NW + gi];
        a0 -= (double)sp_fast(xc);
    }

    // block reduction of the 7 register accumulators (shuffle + shared, no atomics)
    #pragma unroll
    for (int o = 16; o; o >>= 1) {
        a0 += __shfl_down_sync(0xffffffffu, a0, o);
        a1 += __shfl_down_sync(0xffffffffu, a1, o);
        a2 += __shfl_down_sync(0xffffffffu, a2, o);
        a3 += __shfl_down_sync(0xffffffffu, a3, o);
        a4 += __shfl_down_sync(0xffffffffu, a4, o);
        a5 += __shfl_down_sync(0xffffffffu, a5, o);
        a6 += __shfl_down_sync(0xffffffffu, a6, o);
    }
    if (lane == 0) {
        s_part[wid][0] = a0; s_part[wid][1] = a1; s_part[wid][2] = a2;
        s_part[wid][3] = a3; s_part[wid][4] = a4; s_part[wid][5] = a5;
        s_part[wid][6] = a6;
    }
    __syncthreads();

    if (tid == 0) {
        double c0 = 0, c1 = 0, c2 = 0, c3 = 0, c4 = 0, c5 = 0, c6 = 0;
        #pragma unroll
        for (int w = 0; w < NWARP; w++) {
            c0 += s_part[w][0]; c1 += s_part[w][1]; c2 += s_part[w][2];
            c3 += s_part[w][3]; c4 += s_part[w][4]; c5 += s_part[w][5];
            c6 += s_part[w][6];
        }
        double S0   = g_S0 + c0;                       // k_dense completed before this kernel
        g_S0 = 0.0;                                    // reset for next graph replay
        double nobj = (double)s_nObj;
        double cnt  = (double)CELLS - (double)(s_nObj + s_nIgn);
        double loss = (c2 + c3 + c4 + c5 + c1 + c6 / (double)BB) / nobj
                    + S0 / cnt;
        out[0] = (float)loss;
    }
}

extern "C" void kernel_launch(void* const* d_in, const int* in_sizes, int n_in,
                              void* d_out, int out_size) {
    const float* x  = (const float*)d_in[0];
    const float* tg = (const float*)d_in[1];
    const float* an = (const float*)d_in[2];
    k_dense<<<NB_DENSE, TPB>>>(x);
    k_sparse<<<1, TPB>>>(x, tg, an, (float*)d_out);
}

// round 5
// speedup vs baseline: 1.6851x; 1.0914x over previous
#include <cuda_runtime.h>
#include <math.h>

// Fixed problem shapes
#define BB    8
#define NA    5
#define NC    8
#define NH    192
#define NW    192
#define TT    50
#define ATTRS 15                 // 7 + NC
#define NHW   (NH*NW)            // 36864
#define CELLS (BB*NA*NHW)        // 1,474,560
#define NT    (BB*TT)            // 400
#define NIGN  (NT*NA)            // 2000

#define TPB       256
#define CPT       8
#define NB_DENSE  (CELLS/(CPT*TPB))   // 720 (exact)
#define NB_TOTAL  (NB_DENSE+1)        // 721
#define HASH_SZ   4096
#define HASH_MASK (HASH_SZ-1)
#define NWARP     (TPB/32)

// ---- persistent device scratch (finisher resets each run -> replay-safe) ----
__device__ double   g_S0 = 0.0;
__device__ float    g_cr0, g_cr1, g_cr2, g_cr3, g_cr4, g_cr5, g_cr6;
__device__ int      g_nObjG, g_removedG;
__device__ unsigned g_ticket = 0;

__device__ __forceinline__ float sp_fast(float v) {   // softplus == bce0 (clip never binds for |v|<16)
    return fmaxf(v, 0.f) + __logf(1.f + __expf(-fabsf(v)));
}
__device__ __forceinline__ float sigf(float v) {
    return 1.f / (1.f + __expf(-v));
}
__device__ __forceinline__ unsigned hash_cell(int cell) {
    return (((unsigned)cell * 2654435761u) >> 16) & HASH_MASK;
}

__global__ void __launch_bounds__(TPB)
fused(const float* __restrict__ x,
      const float* __restrict__ tg,
      const float* __restrict__ anchors,
      float* __restrict__ out)
{
    __shared__ int   s_hash[HASH_SZ];
    __shared__ int   s_meta[NT];      // valid<<28 | best<<16 | gj<<8 | gi
    __shared__ int   s_label[NT];
    __shared__ float s_fx[NT], s_fy[NT], s_tw[NT], s_th[NT], s_gw[NT], s_gh[NT];
    __shared__ float s_red[NWARP][8];
    __shared__ int   s_nObj, s_nIgn;
    __shared__ float s_anchor[2*NA];

    const int tid  = threadIdx.x;
    const int bid  = blockIdx.x;
    const int lane = tid & 31;
    const int wid  = tid >> 5;

    if (bid < NB_DENSE) {
        // ========== dense: softplus sum over conf channel (all-float) ==========
        int c0 = (bid * TPB + tid) * CPT;
        int i0 = c0 % NW;
        int j  = (c0 / NW) % NH;
        int ba = c0 / NHW;
        const float* p = x + ((size_t)ba * ATTRS + 6) * NHW + (size_t)j * NW + i0;
        float4 a = *(const float4*)p;
        float4 b = *(const float4*)(p + 4);
        // sum softplus = sum fmax(v,0) + log(prod(1+e^-|v|))  -> 8 EX2 + 1 LG2
        float smax = fmaxf(a.x,0.f)+fmaxf(a.y,0.f)+fmaxf(a.z,0.f)+fmaxf(a.w,0.f)
                   + fmaxf(b.x,0.f)+fmaxf(b.y,0.f)+fmaxf(b.z,0.f)+fmaxf(b.w,0.f);
        float prod = (1.f+__expf(-fabsf(a.x))) * (1.f+__expf(-fabsf(a.y)))
                   * (1.f+__expf(-fabsf(a.z))) * (1.f+__expf(-fabsf(a.w)))
                   * (1.f+__expf(-fabsf(b.x))) * (1.f+__expf(-fabsf(b.y)))
                   * (1.f+__expf(-fabsf(b.z))) * (1.f+__expf(-fabsf(b.w)));
        float local = smax + __logf(prod);

        #pragma unroll
        for (int o = 16; o; o >>= 1) local += __shfl_down_sync(0xffffffffu, local, o);
        if (lane == 0) s_red[wid][0] = local;
        __syncthreads();
        if (tid == 0) {
            float bs = 0.f;
            #pragma unroll
            for (int w = 0; w < NWARP; w++) bs += s_red[w][0];
            atomicAdd(&g_S0, (double)bs);            // one REDG.F64 per block
        }
    } else {
        // ========== special block: targets + sparse corrections (all-float accum) ==========
        float a0 = 0.f, a1 = 0.f, a2 = 0.f, a3 = 0.f, a4 = 0.f, a5 = 0.f, a6 = 0.f;

        for (int i = tid; i < HASH_SZ; i += TPB) s_hash[i] = -1;
        if (tid == 0) { s_nObj = 0; s_nIgn = 0; }
        if (tid < 2*NA) s_anchor[tid] = anchors[tid];
        __syncthreads();

        // phase 0: per-target precompute
        for (int t = tid; t < NT; t += TPB) {
            const float* r = tg + (size_t)t * 5;
            float r0 = r[0], r1 = r[1], r2 = r[2], r3 = r[3], r4 = r[4];
            int valid = ((r0 + r1 + r2 + r3 + r4) != 0.f);
            float gx = r1 * NW, gy = r2 * NH, gw = r3 * NW, gh = r4 * NH;
            int gi = (int)floorf(gx), gj = (int)floorf(gy);
            float bestIou = -1.f; int best = 0; float awb = 1.f, ahb = 1.f;
            #pragma unroll
            for (int a = 0; a < NA; a++) {
                float aw = s_anchor[2*a], ah = s_anchor[2*a+1];
                float inter = fminf(gw, aw) * fminf(gh, ah);
                float iou   = inter / (gw * gh + aw * ah - inter);
                if (iou > bestIou) { bestIou = iou; best = a; awb = aw; ahb = ah; }
            }
            s_meta[t]  = (valid << 28) | (best << 16) | (gj << 8) | gi;
            s_label[t] = (int)r0;
            s_fx[t] = gx - floorf(gx);
            s_fy[t] = gy - floorf(gy);
            s_tw[t] = logf(gw / awb + 1e-16f);
            s_th[t] = logf(gh / ahb + 1e-16f);
            s_gw[t] = gw; s_gh[t] = gh;
        }
        __syncthreads();

        // phase 1: winners (last-write-wins) -> hash insert + obj-cell work
        for (int t = tid; t < NT; t += TPB) {
            int meta = s_meta[t];
            if (!(meta >> 28)) continue;
            int b = t / TT;
            bool winner = true;
            int tEnd = (b + 1) * TT;
            for (int t2 = t + 1; t2 < tEnd; t2++)
                if (s_meta[t2] == meta) { winner = false; break; }
            if (!winner) continue;

            int best = (meta >> 16) & 0xff, gj = (meta >> 8) & 0xff, gi = meta & 0xff;
            int cell = ((b * NA + best) * NH + gj) * NW + gi;
            unsigned h = hash_cell(cell);
            while (atomicCAS(&s_hash[h], -1, cell) != -1) h = (h + 1) & HASH_MASK;
            atomicAdd(&s_nObj, 1);

            size_t base = (size_t)(b * NA + best) * ATTRS * NHW + (size_t)gj * NW + gi;
            float x0 = x[base];
            float x1 = x[base + (size_t)NHW];
            float x2 = x[base + 2 * (size_t)NHW];
            float x3 = x[base + 3 * (size_t)NHW];
            float xc = x[base + 6 * (size_t)NHW];

            float dx = sigf(x0) - s_fx[t];
            float dy = sigf(x1) - s_fy[t];
            float dw = x2 - s_tw[t];
            float dh = x3 - s_th[t];
            a2 += dx * dx;
            a3 += dy * dy;
            a4 += dw * dw;
            a5 += dh * dh;
            a1 += sp_fast(-xc);                     // -log p (tconf=1 bce)
            a0 -= sp_fast(xc);                      // remove bce0 from noobj sum

            // class CE: log_softmax over sigmoid(logits)
            float sv[NC]; float m = -1e30f;
            #pragma unroll
            for (int c = 0; c < NC; c++) {
                sv[c] = sigf(x[base + (size_t)(7 + c) * NHW]);
                m = fmaxf(m, sv[c]);
            }
            float sum = 0.f;
            #pragma unroll
            for (int c = 0; c < NC; c++) sum += __expf(sv[c] - m);
            a6 += m + __logf(sum) - sv[s_label[t]];
        }
        __syncthreads();   // all obj cells in hash before ignore probes

        // phase 2: ignore cells (iou > 0.6), dedup via hash; obj beats ignore
        for (int k = tid; k < NIGN; k += TPB) {
            int t = k / NA, a = k % NA;
            int meta = s_meta[t];
            if (!(meta >> 28)) continue;
            float aw = s_anchor[2*a], ah = s_anchor[2*a+1];
            float gw = s_gw[t], gh = s_gh[t];
            float inter = fminf(gw, aw) * fminf(gh, ah);
            float iou   = inter / (gw * gh + aw * ah - inter);
            if (!(iou > 0.6f)) continue;
            int b = t / TT, gj = (meta >> 8) & 0xff, gi = meta & 0xff;
            int cell = ((b * NA + a) * NH + gj) * NW + gi;
            unsigned h = hash_cell(cell);
            bool mine = false;
            while (true) {
                int prev = atomicCAS(&s_hash[h], -1, cell);
                if (prev == -1)   { mine = true; break; }
                if (prev == cell) break;                    // dup or obj cell
                h = (h + 1) & HASH_MASK;
            }
            if (!mine) continue;
            atomicAdd(&s_nIgn, 1);
            float xc = x[((size_t)(b * NA + a) * ATTRS + 6) * NHW + (size_t)gj * NW + gi];
            a0 -= sp_fast(xc);
        }

        // block reduction in FLOAT (no FP64 tree)
        #pragma unroll
        for (int o = 16; o; o >>= 1) {
            a0 += __shfl_down_sync(0xffffffffu, a0, o);
            a1 += __shfl_down_sync(0xffffffffu, a1, o);
            a2 += __shfl_down_sync(0xffffffffu, a2, o);
            a3 += __shfl_down_sync(0xffffffffu, a3, o);
            a4 += __shfl_down_sync(0xffffffffu, a4, o);
            a5 += __shfl_down_sync(0xffffffffu, a5, o);
            a6 += __shfl_down_sync(0xffffffffu, a6, o);
        }
        if (lane == 0) {
            s_red[wid][0] = a0; s_red[wid][1] = a1; s_red[wid][2] = a2;
            s_red[wid][3] = a3; s_red[wid][4] = a4; s_red[wid][5] = a5;
            s_red[wid][6] = a6;
        }
        __syncthreads();
        if (tid == 0) {
            float c0 = 0.f, c1 = 0.f, c2 = 0.f, c3 = 0.f, c4 = 0.f, c5 = 0.f, c6 = 0.f;
            #pragma unroll
            for (int w = 0; w < NWARP; w++) {
                c0 += s_red[w][0]; c1 += s_red[w][1]; c2 += s_red[w][2];
                c3 += s_red[w][3]; c4 += s_red[w][4]; c5 += s_red[w][5];
                c6 += s_red[w][6];
            }
            g_cr0 = c0; g_cr1 = c1; g_cr2 = c2; g_cr3 = c3;
            g_cr4 = c4; g_cr5 = c5; g_cr6 = c6;
            g_nObjG    = s_nObj;
            g_removedG = s_nObj + s_nIgn;
        }
    }

    // ========== ticket: last block finalizes (thread 0 only) ==========
    __syncthreads();
    if (tid == 0) {
        __threadfence();
        unsigned old = atomicAdd(&g_ticket, 1u);
        if (old == (unsigned)(NB_TOTAL - 1)) {
            double S0   = atomicAdd(&g_S0, 0.0) + (double)*(volatile float*)&g_cr0;
            double nobj = (double)*(volatile int*)&g_nObjG;
            double cnt  = (double)CELLS - (double)*(volatile int*)&g_removedG;
            double objs = (double)*(volatile float*)&g_cr2 + (double)*(volatile float*)&g_cr3
                        + (double)*(volatile float*)&g_cr4 + (double)*(volatile float*)&g_cr5
                        + (double)*(volatile float*)&g_cr1
                        + (double)*(volatile float*)&g_cr6 / (double)BB;
            out[0] = (float)(objs / nobj + S0 / cnt);
            // reset for next graph replay
            g_S0 = 0.0;
            g_ticket = 0u;
        }
    }
}

extern "C" void kernel_launch(void* const* d_in, const int* in_sizes, int n_in,
                              void* d_out, int out_size) {
    const float* x  = (const float*)d_in[0];
    const float* tg = (const float*)d_in[1];
    const float* an = (const float*)d_in[2];
    fused<<<NB_TOTAL, TPB>>>(x, tg, an, (float*)d_out);
}

// round 6
// speedup vs baseline: 7.7327x; 4.5888x over previous
#include <cuda_runtime.h>
#include <math.h>

// Fixed problem shapes
#define BB    8
#define NA    5
#define NC    8
#define NH    192
#define NW    192
#define TT    50
#define ATTRS 15                 // 7 + NC
#define NHW   (NH*NW)            // 36864
#define CELLS (BB*NA*NHW)        // 1,474,560
#define NT    (BB*TT)            // 400
#define NIGN  (NT*NA)            // 2000
#define NPAIR (BB*TT*TT)         // 20000 ordered pairs

#define TPB       1024
#define CPT       8
#define NB_DENSE  (CELLS/(CPT*TPB))   // 180 (exact)
#define NB_TOTAL  (NB_DENSE+1)        // 181
#define HASH_SZ   4096
#define HASH_MASK (HASH_SZ-1)
#define NWARP     (TPB/32)            // 32

// ---- persistent device scratch (finisher resets each run -> replay-safe) ----
__device__ double   g_S0 = 0.0;
__device__ float    g_cr0, g_cr1, g_cr2, g_cr3, g_cr4, g_cr5, g_cr6;
__device__ int      g_nObjG, g_removedG;
__device__ unsigned g_ticket = 0;

__device__ __forceinline__ float sp_fast(float v) {   // softplus == bce0 (clip never binds for |v|<16)
    return fmaxf(v, 0.f) + __logf(1.f + __expf(-fabsf(v)));
}
__device__ __forceinline__ float sigf(float v) {
    return 1.f / (1.f + __expf(-v));
}
__device__ __forceinline__ unsigned hash_cell(int cell) {
    return (((unsigned)cell * 2654435761u) >> 16) & HASH_MASK;
}

__global__ void __launch_bounds__(TPB)
fused(const float* __restrict__ x,
      const float* __restrict__ tg,
      const float* __restrict__ anchors,
      float* __restrict__ out)
{
    __shared__ int   s_hash[HASH_SZ];
    __shared__ int   s_meta[NT];      // valid<<28 | best<<16 | gj<<8 | gi
    __shared__ int   s_label[NT];
    __shared__ unsigned char s_loser[NT];
    __shared__ float s_fx[NT], s_fy[NT], s_tw[NT], s_th[NT], s_gw[NT], s_gh[NT];
    __shared__ float s_red[NWARP][8];
    __shared__ int   s_nObj, s_nIgn;
    __shared__ float s_anchor[2*NA];

    const int tid  = threadIdx.x;
    const int bid  = blockIdx.x;
    const int lane = tid & 31;
    const int wid  = tid >> 5;

    if (bid < NB_DENSE) {
        // ========== dense: softplus sum over conf channel ==========
        int c0 = (bid * TPB + tid) * CPT;
        int i0 = c0 % NW;
        int j  = (c0 / NW) % NH;
        int ba = c0 / NHW;
        const float* p = x + ((size_t)ba * ATTRS + 6) * NHW + (size_t)j * NW + i0;
        float4 a = *(const float4*)p;
        float4 b = *(const float4*)(p + 4);
        float smax = fmaxf(a.x,0.f)+fmaxf(a.y,0.f)+fmaxf(a.z,0.f)+fmaxf(a.w,0.f)
                   + fmaxf(b.x,0.f)+fmaxf(b.y,0.f)+fmaxf(b.z,0.f)+fmaxf(b.w,0.f);
        float prod = (1.f+__expf(-fabsf(a.x))) * (1.f+__expf(-fabsf(a.y)))
                   * (1.f+__expf(-fabsf(a.z))) * (1.f+__expf(-fabsf(a.w)))
                   * (1.f+__expf(-fabsf(b.x))) * (1.f+__expf(-fabsf(b.y)))
                   * (1.f+__expf(-fabsf(b.z))) * (1.f+__expf(-fabsf(b.w)));
        float local = smax + __logf(prod);

        #pragma unroll
        for (int o = 16; o; o >>= 1) local += __shfl_down_sync(0xffffffffu, local, o);
        if (lane == 0) s_red[wid][0] = local;
        __syncthreads();
        if (tid == 0) {
            float bs = 0.f;
            #pragma unroll
            for (int w = 0; w < NWARP; w++) bs += s_red[w][0];
            atomicAdd(&g_S0, (double)bs);            // one REDG.F64 per block
        }
    } else {
        // ========== special block: fully parallel sparse path ==========
        float a0 = 0.f, a1 = 0.f, a2 = 0.f, a3 = 0.f, a4 = 0.f, a5 = 0.f, a6 = 0.f;

        for (int i = tid; i < HASH_SZ; i += TPB) s_hash[i] = -1;
        if (tid < NT) s_loser[tid] = 0;
        if (tid == 0) { s_nObj = 0; s_nIgn = 0; }
        if (tid < 2*NA) s_anchor[tid] = anchors[tid];
        __syncthreads();

        // phase 0: one thread per target
        if (tid < NT) {
            const int t = tid;
            const float* r = tg + (size_t)t * 5;
            float r0 = r[0], r1 = r[1], r2 = r[2], r3 = r[3], r4 = r[4];
            int valid = ((r0 + r1 + r2 + r3 + r4) != 0.f);
            float gx = r1 * NW, gy = r2 * NH, gw = r3 * NW, gh = r4 * NH;
            int gi = (int)floorf(gx), gj = (int)floorf(gy);
            float bestIou = -1.f; int best = 0; float awb = 1.f, ahb = 1.f;
            #pragma unroll
            for (int a = 0; a < NA; a++) {
                float aw = s_anchor[2*a], ah = s_anchor[2*a+1];
                float inter = fminf(gw, aw) * fminf(gh, ah);
                float iou   = inter / (gw * gh + aw * ah - inter);
                if (iou > bestIou) { bestIou = iou; best = a; awb = aw; ahb = ah; }
            }
            s_meta[t]  = (valid << 28) | (best << 16) | (gj << 8) | gi;
            s_label[t] = (int)r0;
            s_fx[t] = gx - floorf(gx);
            s_fy[t] = gy - floorf(gy);
            s_tw[t] = logf(gw / awb + 1e-16f);
            s_th[t] = logf(gh / ahb + 1e-16f);
            s_gw[t] = gw; s_gh[t] = gh;
        }
        __syncthreads();

        // phase 0.5: parallel last-write-wins — mark losers via pair comparisons
        for (int p = tid; p < NPAIR; p += TPB) {
            int b  = p / (TT*TT);
            int r  = p - b * (TT*TT);
            int ti = r / TT;            // earlier candidate
            int tj = r - ti * TT;       // later candidate
            if (tj > ti) {
                int t1 = b * TT + ti, t2 = b * TT + tj;
                int m1 = s_meta[t1];
                if ((m1 >> 28) && m1 == s_meta[t2]) s_loser[t1] = 1;  // benign race
            }
        }
        __syncthreads();

        // phase 1: winners -> hash insert + obj-cell work (one thread per target)
        if (tid < NT) {
            const int t = tid;
            int meta = s_meta[t];
            if ((meta >> 28) && !s_loser[t]) {
                int b = t / TT;
                int best = (meta >> 16) & 0xff, gj = (meta >> 8) & 0xff, gi = meta & 0xff;
                int cell = ((b * NA + best) * NH + gj) * NW + gi;
                unsigned h = hash_cell(cell);
                while (atomicCAS(&s_hash[h], -1, cell) != -1) h = (h + 1) & HASH_MASK;
                atomicAdd(&s_nObj, 1);

                size_t base = (size_t)(b * NA + best) * ATTRS * NHW + (size_t)gj * NW + gi;
                float x0 = x[base];
                float x1 = x[base + (size_t)NHW];
                float x2 = x[base + 2 * (size_t)NHW];
                float x3 = x[base + 3 * (size_t)NHW];
                float xc = x[base + 6 * (size_t)NHW];

                float dx = sigf(x0) - s_fx[t];
                float dy = sigf(x1) - s_fy[t];
                float dw = x2 - s_tw[t];
                float dh = x3 - s_th[t];
                a2 += dx * dx;
                a3 += dy * dy;
                a4 += dw * dw;
                a5 += dh * dh;
                a1 += sp_fast(-xc);                 // -log p (tconf=1 bce)
                a0 -= sp_fast(xc);                  // remove bce0 from noobj sum

                // class CE: log_softmax over sigmoid(logits)
                float sv[NC]; float m = -1e30f;
                #pragma unroll
                for (int c = 0; c < NC; c++) {
                    sv[c] = sigf(x[base + (size_t)(7 + c) * NHW]);
                    m = fmaxf(m, sv[c]);
                }
                float sum = 0.f;
                #pragma unroll
                for (int c = 0; c < NC; c++) sum += __expf(sv[c] - m);
                a6 += m + __logf(sum) - sv[s_label[t]];
            }
        }
        __syncthreads();   // all obj cells in hash before ignore probes

        // phase 2: ignore cells (iou > 0.6), dedup via hash; obj beats ignore
        for (int k = tid; k < NIGN; k += TPB) {
            int t = k / NA, a = k - (k / NA) * NA;
            int meta = s_meta[t];
            if (!(meta >> 28)) continue;
            float aw = s_anchor[2*a], ah = s_anchor[2*a+1];
            float gw = s_gw[t], gh = s_gh[t];
            float inter = fminf(gw, aw) * fminf(gh, ah);
            float iou   = inter / (gw * gh + aw * ah - inter);
            if (!(iou > 0.6f)) continue;
            int b = t / TT, gj = (meta >> 8) & 0xff, gi = meta & 0xff;
            int cell = ((b * NA + a) * NH + gj) * NW + gi;
            unsigned h = hash_cell(cell);
            bool mine = false;
            while (true) {
                int prev = atomicCAS(&s_hash[h], -1, cell);
                if (prev == -1)   { mine = true; break; }
                if (prev == cell) break;            // dup or obj cell
                h = (h + 1) & HASH_MASK;
            }
            if (!mine) continue;
            atomicAdd(&s_nIgn, 1);
            float xc = x[((size_t)(b * NA + a) * ATTRS + 6) * NHW + (size_t)gj * NW + gi];
            a0 -= sp_fast(xc);
        }

        // block reduction in float
        #pragma unroll
        for (int o = 16; o; o >>= 1) {
            a0 += __shfl_down_sync(0xffffffffu, a0, o);
            a1 += __shfl_down_sync(0xffffffffu, a1, o);
            a2 += __shfl_down_sync(0xffffffffu, a2, o);
            a3 += __shfl_down_sync(0xffffffffu, a3, o);
            a4 += __shfl_down_sync(0xffffffffu, a4, o);
            a5 += __shfl_down_sync(0xffffffffu, a5, o);
            a6 += __shfl_down_sync(0xffffffffu, a6, o);
        }
        if (lane == 0) {
            s_red[wid][0] = a0; s_red[wid][1] = a1; s_red[wid][2] = a2;
            s_red[wid][3] = a3; s_red[wid][4] = a4; s_red[wid][5] = a5;
            s_red[wid][6] = a6;
        }
        __syncthreads();
        if (tid == 0) {
            float c0 = 0.f, c1 = 0.f, c2 = 0.f, c3 = 0.f, c4 = 0.f, c5 = 0.f, c6 = 0.f;
            #pragma unroll
            for (int w = 0; w < NWARP; w++) {
                c0 += s_red[w][0]; c1 += s_red[w][1]; c2 += s_red[w][2];
                c3 += s_red[w][3]; c4 += s_red[w][4]; c5 += s_red[w][5];
                c6 += s_red[w][6];
            }
            g_cr0 = c0; g_cr1 = c1; g_cr2 = c2; g_cr3 = c3;
            g_cr4 = c4; g_cr5 = c5; g_cr6 = c6;
            g_nObjG    = s_nObj;
            g_removedG = s_nObj + s_nIgn;
        }
    }

    // ========== ticket: last block finalizes ==========
    __syncthreads();
    if (tid == 0) {
        __threadfence();
        unsigned old = atomicAdd(&g_ticket, 1u);
        if (old == (unsigned)(NB_TOTAL - 1)) {
            double S0   = atomicAdd(&g_S0, 0.0) + (double)*(volatile float*)&g_cr0;
            double nobj = (double)*(volatile int*)&g_nObjG;
            double cnt  = (double)CELLS - (double)*(volatile int*)&g_removedG;
            double objs = (double)*(volatile float*)&g_cr2 + (double)*(volatile float*)&g_cr3
                        + (double)*(volatile float*)&g_cr4 + (double)*(volatile float*)&g_cr5
                        + (double)*(volatile float*)&g_cr1
                        + (double)*(volatile float*)&g_cr6 / (double)BB;
            out[0] = (float)(objs / nobj + S0 / cnt);
            g_S0 = 0.0;
            g_ticket = 0u;
        }
    }
}

extern "C" void kernel_launch(void* const* d_in, const int* in_sizes, int n_in,
                              void* d_out, int out_size) {
    const float* x  = (const float*)d_in[0];
    const float* tg = (const float*)d_in[1];
    const float* an = (const float*)d_in[2];
    fused<<<NB_TOTAL, TPB>>>(x, tg, an, (float*)d_out);
}